// round 3
// baseline (speedup 1.0000x reference)
#include <cuda_runtime.h>

#define D 128
constexpr int MAXN = 100000;
constexpr int MAXE = 1600000;

// ---------------- scratch (device globals: allocation-free) ----------------
__device__ int   g_deg[MAXN];
__device__ int   g_fill[MAXN];
__device__ float g_dinv[MAXN];
__device__ int   g_rowptr[MAXN + 1];
__device__ int   g_src[MAXE];
__device__ __align__(16) float g_w[MAXE];
__device__ __align__(16) float g_tmp[(size_t)MAXN * D];   // GEMM output
__device__ __align__(16) float g_h[(size_t)MAXN * D];     // layer activations

// ---------------- preprocessing ----------------
__global__ void k_zero(int N) {
    int i = blockIdx.x * blockDim.x + threadIdx.x;
    if (i < N) { g_deg[i] = 0; g_fill[i] = 0; }
}

__global__ void k_hist(const int* __restrict__ ei, int E) {
    int e = blockIdx.x * blockDim.x + threadIdx.x;
    if (e < E) atomicAdd(&g_deg[ei[E + e]], 1);
}

__global__ void k_dinv(int N) {
    int i = blockIdx.x * blockDim.x + threadIdx.x;
    if (i < N) g_dinv[i] = rsqrtf((float)(g_deg[i] + 1));  // +1 self-loop
}

// single-block exclusive scan of g_deg -> g_rowptr
__global__ void k_scan(int N) {
    __shared__ int s[1024];
    int t = threadIdx.x;
    int chunk = (N + 1023) / 1024;
    int lo = t * chunk;
    int hi = lo + chunk; if (hi > N) hi = N; if (lo > N) lo = N;
    int sum = 0;
    for (int i = lo; i < hi; i++) sum += g_deg[i];
    s[t] = sum;
    __syncthreads();
    for (int off = 1; off < 1024; off <<= 1) {
        int v = (t >= off) ? s[t - off] : 0;
        __syncthreads();
        s[t] += v;
        __syncthreads();
    }
    int prefix = (t == 0) ? 0 : s[t - 1];
    for (int i = lo; i < hi; i++) {
        g_rowptr[i] = prefix;
        prefix += g_deg[i];
    }
    if (t == 1023) g_rowptr[N] = s[1023];
}

__global__ void k_fill(const int* __restrict__ ei, int E) {
    int e = blockIdx.x * blockDim.x + threadIdx.x;
    if (e < E) {
        int r = ei[e];
        int c = ei[E + e];
        int p = g_rowptr[c] + atomicAdd(&g_fill[c], 1);
        g_src[p] = r;
        g_w[p]   = g_dinv[r] * g_dinv[c];
    }
}

// ---------------- GEMM: g_tmp[N,128] = A[N,128] @ W[128,128] ----------------
// A = x (use_x=1) or g_h (use_x=0). 128x128 tile, 8x8 microtile, BK=16, 256 thr.
__global__ __launch_bounds__(256) void k_gemm(const float* __restrict__ x,
                                              const float* __restrict__ W,
                                              int N, int use_x) {
    __shared__ float As[16 * 128];   // As[k][row]
    __shared__ float Bs[16 * 128];   // Bs[k][col]
    const float* A = use_x ? x : (const float*)g_h;
    int tid = threadIdx.x;
    int tx = tid & 15;               // col group
    int ty = tid >> 4;               // row group
    int row0 = blockIdx.x * 128;

    int ar  = tid >> 1;              // row this thread loads (0..127)
    int akq = (tid & 1) * 8;         // k offset within tile (0 or 8)

    float acc[8][8];
#pragma unroll
    for (int i = 0; i < 8; i++)
#pragma unroll
        for (int j = 0; j < 8; j++) acc[i][j] = 0.f;

    const float4* W4 = (const float4*)W;
    float4* Bs4 = (float4*)Bs;

    for (int k0 = 0; k0 < 128; k0 += 16) {
        Bs4[tid]       = W4[k0 * 32 + tid];
        Bs4[tid + 256] = W4[k0 * 32 + 256 + tid];
        float4 a0 = make_float4(0.f, 0.f, 0.f, 0.f);
        float4 a1 = make_float4(0.f, 0.f, 0.f, 0.f);
        int grow = row0 + ar;
        if (grow < N) {
            const float4* Ar = (const float4*)(A + (size_t)grow * D + k0 + akq);
            a0 = Ar[0];
            a1 = Ar[1];
        }
        As[(akq + 0) * 128 + ar] = a0.x;
        As[(akq + 1) * 128 + ar] = a0.y;
        As[(akq + 2) * 128 + ar] = a0.z;
        As[(akq + 3) * 128 + ar] = a0.w;
        As[(akq + 4) * 128 + ar] = a1.x;
        As[(akq + 5) * 128 + ar] = a1.y;
        As[(akq + 6) * 128 + ar] = a1.z;
        As[(akq + 7) * 128 + ar] = a1.w;
        __syncthreads();

#pragma unroll
        for (int kk = 0; kk < 16; kk++) {
            float4 av0 = *(const float4*)&As[kk * 128 + ty * 8];
            float4 av1 = *(const float4*)&As[kk * 128 + ty * 8 + 4];
            float4 bv0 = *(const float4*)&Bs[kk * 128 + tx * 8];
            float4 bv1 = *(const float4*)&Bs[kk * 128 + tx * 8 + 4];
            float a[8] = {av0.x, av0.y, av0.z, av0.w, av1.x, av1.y, av1.z, av1.w};
            float b[8] = {bv0.x, bv0.y, bv0.z, bv0.w, bv1.x, bv1.y, bv1.z, bv1.w};
#pragma unroll
            for (int i = 0; i < 8; i++)
#pragma unroll
                for (int j = 0; j < 8; j++)
                    acc[i][j] = fmaf(a[i], b[j], acc[i][j]);
        }
        __syncthreads();
    }

#pragma unroll
    for (int i = 0; i < 8; i++) {
        int grow = row0 + ty * 8 + i;
        if (grow < N) {
            float4* Cp = (float4*)(g_tmp + (size_t)grow * D + tx * 8);
            Cp[0] = make_float4(acc[i][0], acc[i][1], acc[i][2], acc[i][3]);
            Cp[1] = make_float4(acc[i][4], acc[i][5], acc[i][6], acc[i][7]);
        }
    }
}

// ---------------- aggregation (gather-side, CSR by destination) ----------------
// one warp per node; lane covers 4 consecutive feature columns (float4)
__global__ void k_agg(const float* __restrict__ bias, int N) {
    int gt   = blockIdx.x * blockDim.x + threadIdx.x;
    int v    = gt >> 5;
    int lane = gt & 31;
    if (v >= N) return;

    float s  = g_dinv[v];
    float w0 = s * s;
    float4 m = ((const float4*)(g_tmp + (size_t)v * D))[lane];
    float ax = m.x * w0, ay = m.y * w0, az = m.z * w0, aw = m.w * w0;

    int beg = g_rowptr[v];
    int end = g_rowptr[v + 1];
    int j = beg;
    if (j < end) {
        int   src = __ldg(&g_src[j]);
        float w   = __ldg(&g_w[j]);
        for (; j + 1 < end; j++) {
            int   nsrc = __ldg(&g_src[j + 1]);
            float nw   = __ldg(&g_w[j + 1]);
            float4 mm  = ((const float4*)(g_tmp + (size_t)src * D))[lane];
            ax = fmaf(mm.x, w, ax);
            ay = fmaf(mm.y, w, ay);
            az = fmaf(mm.z, w, az);
            aw = fmaf(mm.w, w, aw);
            src = nsrc;
            w   = nw;
        }
        float4 mm = ((const float4*)(g_tmp + (size_t)src * D))[lane];
        ax = fmaf(mm.x, w, ax);
        ay = fmaf(mm.y, w, ay);
        az = fmaf(mm.z, w, az);
        aw = fmaf(mm.w, w, aw);
    }

    float4 b = ((const float4*)bias)[lane];
    float4 o;
    o.x = fmaxf(ax + b.x, 0.f);
    o.y = fmaxf(ay + b.y, 0.f);
    o.z = fmaxf(az + b.z, 0.f);
    o.w = fmaxf(aw + b.w, 0.f);
    ((float4*)(g_h + (size_t)v * D))[lane] = o;
}

// ---------------- pool + linear ----------------
__device__ __forceinline__ int lb(const int* a, int n, int key) {
    int lo = 0, hi = n;
    while (lo < hi) {
        int m = (lo + hi) >> 1;
        if (a[m] < key) lo = m + 1; else hi = m;
    }
    return lo;
}

__global__ void k_pool(const int* __restrict__ batch,
                       const float* __restrict__ Wl,
                       const float* __restrict__ bl,
                       float* __restrict__ out, int N) {
    int g = blockIdx.x;
    __shared__ int bounds[2];
    if (threadIdx.x == 0) bounds[0] = lb(batch, N, g);
    if (threadIdx.x == 1) bounds[1] = lb(batch, N, g + 1);
    __syncthreads();
    int lo = bounds[0], hi = bounds[1];
    int t = threadIdx.x;   // feature column
    float sum = 0.f;
    for (int v = lo; v < hi; v++) sum += g_h[(size_t)v * D + t];
    float cnt  = (float)(hi - lo);
    float mean = sum / fmaxf(cnt, 1.f);
    float p    = mean * Wl[t];
    __shared__ float red[128];
    red[t] = p;
    __syncthreads();
    for (int off = 64; off > 0; off >>= 1) {
        if (t < off) red[t] += red[t + off];
        __syncthreads();
    }
    if (t == 0) out[g] = red[0] + bl[0];
}

// ---------------- launch ----------------
extern "C" void kernel_launch(void* const* d_in, const int* in_sizes, int n_in,
                              void* d_out, int out_size) {
    // Identify inputs by element count (all distinct):
    // x: N*128 (12.8M), edge_index: 2E (3.2M), batch: N (100k),
    // Ws: 4*128*128 (65536), bs: 4*128 (512), Wl: 128, bl: 1
    const float* x     = nullptr;
    const int*   ei    = nullptr;
    const int*   batch = nullptr;
    const float* Ws    = nullptr;
    const float* bs    = nullptr;
    const float* Wl    = nullptr;
    const float* bl    = nullptr;
    int N = 0, E = 0;

    // first pass: find the largest size = x, second largest multiple = edges
    long long sx = 0;
    for (int i = 0; i < n_in; i++) if ((long long)in_sizes[i] > sx) sx = in_sizes[i];
    N = (int)(sx / D);
    for (int i = 0; i < n_in; i++) {
        long long s = in_sizes[i];
        if (s == sx)                x     = (const float*)d_in[i];
        else if (s == (long long)N) batch = (const int*)d_in[i];
        else if (s == 4LL * D * D)  Ws    = (const float*)d_in[i];
        else if (s == 4LL * D)      bs    = (const float*)d_in[i];
        else if (s == D)            Wl    = (const float*)d_in[i];
        else if (s == 1)            bl    = (const float*)d_in[i];
        else                        { ei = (const int*)d_in[i]; E = (int)(s / 2); }
    }
    float* out = (float*)d_out;

    k_zero<<<(N + 255) / 256, 256>>>(N);
    k_hist<<<(E + 255) / 256, 256>>>(ei, E);
    k_dinv<<<(N + 255) / 256, 256>>>(N);
    k_scan<<<1, 1024>>>(N);
    k_fill<<<(E + 255) / 256, 256>>>(ei, E);

    int gblocks = (N + 127) / 128;
    for (int l = 0; l < 4; l++) {
        k_gemm<<<gblocks, 256>>>(x, Ws + (size_t)l * D * D, N, l == 0 ? 1 : 0);
        int aggblocks = (N * 32 + 255) / 256;
        k_agg<<<aggblocks, 256>>>(bs + (size_t)l * D, N);
    }

    k_pool<<<out_size, 128>>>(batch, Wl, bl, out, N);
}